// round 7
// baseline (speedup 1.0000x reference)
#include <cuda_runtime.h>
#include <cstdint>

// TopK-magnitude masking per row. x: (4096, 8192) fp32, K = 819.
// out[r,c] = x[r,c] if |x[r,c]| >= (K-th largest |x| in row r) else 0.
//
// One CTA per row, 512 threads, row staged in SMEM (32 regs -> 4 CTAs/SM).
// Exact K-th largest |x| via 3-pass radix select (11+10+10 bits) on bits(|x|).
// Pass 2 compacts the surviving candidates (typically ~300 of 8192) into a
// small buffer, so pass 3 touches only candidates instead of the full row.

#define ROWLEN  8192
#define TPB     512
#define VPT     4            // float4 per thread -> 16 floats
#define KSEL    819u
#define NW      (TPB / 32)   // 16 warps
#define CANDMAX 1024

// Suffix-scan + digit select over hist[NBINS].
// Outputs: *sh_digit (selected digit), *sh_k (rank within that digit),
// *sh_cnt (hist count of that digit). Ends with __syncthreads.
template <int NBINS>
__device__ __forceinline__ void suffix_select(
    const unsigned* __restrict__ hist, unsigned k,
    int t, int lane, int wid,
    unsigned* wsum, unsigned* wtail,
    unsigned* sh_digit, unsigned* sh_k, unsigned* sh_cnt)
{
    constexpr int B = NBINS / TPB;        // bins per thread (4 or 2)
    const int base = t * B;
    unsigned loc[B];
    unsigned s = 0u;
#pragma unroll
    for (int j = B - 1; j >= 0; j--) { s += hist[base + j]; loc[j] = s; }

    unsigned p = s;                        // warp suffix scan of chunk totals
#pragma unroll
    for (int off = 1; off < 32; off <<= 1) {
        unsigned n = __shfl_down_sync(0xFFFFFFFFu, p, off);
        if (lane < 32 - off) p += n;
    }
    if (lane == 0) wsum[wid] = p;
    __syncthreads();
    if (t < NW) {
        unsigned q = wsum[t];
        unsigned r = q;
#pragma unroll
        for (int off = 1; off < NW; off <<= 1) {
            unsigned n = __shfl_down_sync(0x0000FFFFu, r, off);
            if (t < NW - off) r += n;
        }
        wtail[t] = r - q;                  // sum of warp totals AFTER warp t
    }
    __syncthreads();
    unsigned beyond = (p - s) + wtail[wid];
#pragma unroll
    for (int j = 0; j < B; j++) {
        unsigned incl = loc[j] + beyond;                          // count(>=d)
        unsigned cnt  = loc[j] - ((j < B - 1) ? loc[j + 1] : 0u); // hist[d]
        unsigned gt   = incl - cnt;                               // count(>d)
        if (incl >= k && gt < k) {
            *sh_digit = (unsigned)(base + j);
            *sh_k     = k - gt;
            *sh_cnt   = cnt;
        }
    }
    __syncthreads();
}

__global__ __launch_bounds__(TPB, 4)
void topk_mask_kernel(const float* __restrict__ x, float* __restrict__ out) {
    __shared__ float    row[ROWLEN];       // 32 KB
    __shared__ unsigned hist[2048];        // 8 KB
    __shared__ unsigned cand[CANDMAX];     // 4 KB (candidate keys)
    __shared__ unsigned wsum[NW];
    __shared__ unsigned wtail[NW];
    __shared__ unsigned sh_digit, sh_k, sh_cnt;
    __shared__ unsigned ccnt;

    const int t    = threadIdx.x;
    const int lane = t & 31;
    const int wid  = t >> 5;
    const size_t row_off = (size_t)blockIdx.x * ROWLEN;
    const float4* __restrict__ px   = reinterpret_cast<const float4*>(x + row_off);
    float4*       __restrict__ po   = reinterpret_cast<float4*>(out + row_off);
    float4*                    prow = reinterpret_cast<float4*>(row);

    // ---- zero histogram (2048 words) ----
    reinterpret_cast<uint4*>(hist)[t] = make_uint4(0u, 0u, 0u, 0u);
    if (t == 0) ccnt = 0u;
    __syncthreads();

    // ---- pass 1 (fused with load): digit = key >> 20 (11 bits) ----
#pragma unroll
    for (int i = 0; i < VPT; i++) {
        float4 a = px[t + i * TPB];
        prow[t + i * TPB] = a;
        atomicAdd(&hist[(__float_as_uint(a.x) & 0x7FFFFFFFu) >> 20], 1u);
        atomicAdd(&hist[(__float_as_uint(a.y) & 0x7FFFFFFFu) >> 20], 1u);
        atomicAdd(&hist[(__float_as_uint(a.z) & 0x7FFFFFFFu) >> 20], 1u);
        atomicAdd(&hist[(__float_as_uint(a.w) & 0x7FFFFFFFu) >> 20], 1u);
    }
    __syncthreads();

    unsigned k = KSEL;
    suffix_select<2048>(hist, k, t, lane, wid, wsum, wtail, &sh_digit, &sh_k, &sh_cnt);
    const unsigned d1 = sh_digit; k = sh_k;
    const unsigned C  = sh_cnt;            // candidates surviving pass 1

    // ---- pass 2 + compaction: digit = bits [10,20), prefix d1 ----
    reinterpret_cast<uint2*>(hist)[t] = make_uint2(0u, 0u);   // 1024 bins
    __syncthreads();
#pragma unroll
    for (int i = 0; i < VPT; i++) {
        float4 a = prow[t + i * TPB];
        const float* fa = reinterpret_cast<const float*>(&a);
#pragma unroll
        for (int c = 0; c < 4; c++) {
            unsigned key = __float_as_uint(fa[c]) & 0x7FFFFFFFu;
            if ((key >> 20) == d1) {
                atomicAdd(&hist[(key >> 10) & 0x3FFu], 1u);
                unsigned idx = atomicAdd(&ccnt, 1u);
                if (idx < CANDMAX) cand[idx] = key;
            }
        }
    }
    __syncthreads();
    suffix_select<1024>(hist, k, t, lane, wid, wsum, wtail, &sh_digit, &sh_k, &sh_cnt);
    const unsigned d2 = sh_digit; k = sh_k;

    // ---- pass 3: digit = bits [0,10), prefix (d1,d2) ----
    const unsigned pref21 = (d1 << 10) | d2;   // == key >> 10 for candidates
    reinterpret_cast<uint2*>(hist)[t] = make_uint2(0u, 0u);
    __syncthreads();
    if (C <= CANDMAX) {
        // candidate path: only C elements (typically a few hundred)
        for (unsigned j = t; j < C; j += TPB) {
            unsigned key = cand[j];
            if ((key >> 10) == pref21)
                atomicAdd(&hist[key & 0x3FFu], 1u);
        }
    } else {
        // overflow fallback: full-row sweep (never taken for Gaussian rows)
#pragma unroll
        for (int i = 0; i < VPT; i++) {
            float4 a = prow[t + i * TPB];
            const float* fa = reinterpret_cast<const float*>(&a);
#pragma unroll
            for (int c = 0; c < 4; c++) {
                unsigned key = __float_as_uint(fa[c]) & 0x7FFFFFFFu;
                if ((key >> 10) == pref21)
                    atomicAdd(&hist[key & 0x3FFu], 1u);
            }
        }
    }
    __syncthreads();
    suffix_select<1024>(hist, k, t, lane, wid, wsum, wtail, &sh_digit, &sh_k, &sh_cnt);

    const unsigned T = (pref21 << 10) | sh_digit;   // K-th largest |x| pattern

    // ---- epilogue: mask from smem, coalesced float4 store ----
#pragma unroll
    for (int i = 0; i < VPT; i++) {
        float4 o = prow[t + i * TPB];
        float* fo = reinterpret_cast<float*>(&o);
#pragma unroll
        for (int c = 0; c < 4; c++) {
            unsigned key = __float_as_uint(fo[c]) & 0x7FFFFFFFu;
            if (key < T) fo[c] = 0.0f;
        }
        po[t + i * TPB] = o;
    }
}

extern "C" void kernel_launch(void* const* d_in, const int* in_sizes, int n_in,
                              void* d_out, int out_size) {
    const float* x = (const float*)d_in[0];
    float* out = (float*)d_out;
    const int rows = in_sizes[0] / ROWLEN;   // 4096
    topk_mask_kernel<<<rows, TPB>>>(x, out);
}